// round 6
// baseline (speedup 1.0000x reference)
#include <cuda_runtime.h>
#include <cuda_bf16.h>
#include <cstdint>
#include <math.h>

// Problem constants (fixed by the dataset)
#define Bb   2
#define Ll   2048
#define Dm   1024
#define Hh   16
#define DhD  64
#define PAD  1536
#define Mrows (Bb * Ll)          // 4096
#define QKVN  (3 * Dm)           // 3072

// ---------------------------------------------------------------------------
// Scratch (device globals; no runtime allocation allowed)
// ---------------------------------------------------------------------------
__device__ float g_qkv[(size_t)Mrows * QKVN];         // 4096 x 3072
__device__ float g_q[(size_t)Bb * Hh * Ll * DhD];     // [B,H,L,Dh]
__device__ float g_k[(size_t)Bb * Hh * Ll * DhD];
__device__ float g_v[(size_t)Bb * Hh * Ll * DhD];
__device__ float g_attn[(size_t)Mrows * Dm];          // [B,L,H*Dh]
// bf16 split buffers (A reused for x then attn; B reused for Wqkv then Wout)
__device__ __nv_bfloat16 g_ah[(size_t)Mrows * Dm];
__device__ __nv_bfloat16 g_al[(size_t)Mrows * Dm];
__device__ __nv_bfloat16 g_bh[(size_t)QKVN * Dm];
__device__ __nv_bfloat16 g_bl[(size_t)QKVN * Dm];

// ---------------------------------------------------------------------------
// mma.sync helpers (baseline PTX features, compile for compute_103)
// ---------------------------------------------------------------------------
__device__ __forceinline__ uint32_t smem_u32(const void* p) {
    uint32_t a;
    asm("{ .reg .u64 t; cvta.to.shared.u64 t, %1; cvt.u32.u64 %0, t; }" : "=r"(a) : "l"(p));
    return a;
}
__device__ __forceinline__ void ldsm_x4(uint32_t r[4], uint32_t addr) {
    asm volatile("ldmatrix.sync.aligned.m8n8.x4.shared.b16 {%0,%1,%2,%3}, [%4];"
                 : "=r"(r[0]), "=r"(r[1]), "=r"(r[2]), "=r"(r[3]) : "r"(addr));
}
__device__ __forceinline__ void mma16816(float c[4], const uint32_t a[4], const uint32_t b[2]) {
    asm volatile("mma.sync.aligned.m16n8k16.row.col.f32.bf16.bf16.f32 "
                 "{%0,%1,%2,%3}, {%4,%5,%6,%7}, {%8,%9}, {%0,%1,%2,%3};"
                 : "+f"(c[0]), "+f"(c[1]), "+f"(c[2]), "+f"(c[3])
                 : "r"(a[0]), "r"(a[1]), "r"(a[2]), "r"(a[3]), "r"(b[0]), "r"(b[1]));
}

// ---------------------------------------------------------------------------
// Kernel: fp32 -> (bf16 hi, bf16 lo) split, 2 elements/thread
// ---------------------------------------------------------------------------
__global__ __launch_bounds__(256)
void split_bf16(const float* __restrict__ X, __nv_bfloat16* __restrict__ H,
                __nv_bfloat16* __restrict__ Lo, int n2)
{
    int i = blockIdx.x * blockDim.x + threadIdx.x;
    if (i >= n2) return;
    float2 x = ((const float2*)X)[i];
    __nv_bfloat16 h0 = __float2bfloat16(x.x);
    __nv_bfloat16 h1 = __float2bfloat16(x.y);
    __nv_bfloat162 hv; hv.x = h0; hv.y = h1;
    __nv_bfloat162 lv;
    lv.x = __float2bfloat16(x.x - __bfloat162float(h0));
    lv.y = __float2bfloat16(x.y - __bfloat162float(h1));
    ((__nv_bfloat162*)H)[i]  = hv;
    ((__nv_bfloat162*)Lo)[i] = lv;
}

// ---------------------------------------------------------------------------
// mma.sync bf16-split GEMM: C[M,N] = (Ah+Al)[M,K] * (Bh+Bl)[N,K]^T + bias
//   = Ah*Bh + Ah*Bl + Al*Bh  (Al*Bl dropped, ~2^-18 relative)
// 128x128 CTA tile, 8 warps (4x2), 32x64 warp tile, K-chunk 32,
// 2 CTAs/SM for load/compute overlap. Rows padded to 40 bf16 (80B) so
// ldmatrix row addresses land on distinct 16B slots mod 128B (conflict-free).
// ---------------------------------------------------------------------------
#define PADW 40

__global__ __launch_bounds__(256, 2)
void gemm_mma_split(const __nv_bfloat16* __restrict__ Ah, const __nv_bfloat16* __restrict__ Al,
                    const __nv_bfloat16* __restrict__ Bh, const __nv_bfloat16* __restrict__ Bl,
                    const float* __restrict__ bias, float* __restrict__ C,
                    int M, int N, int K)
{
    __shared__ __nv_bfloat16 sA[2][128][PADW];   // [hi/lo][row][k]
    __shared__ __nv_bfloat16 sB[2][128][PADW];

    const int tid  = threadIdx.x;
    const int lane = tid & 31;
    const int wid  = tid >> 5;
    const int wm   = wid & 3;        // 0..3 (m)
    const int wn   = wid >> 2;       // 0..1 (n)
    const int m0   = blockIdx.y * 128;
    const int n0   = blockIdx.x * 128;

    float c[2][8][4];
#pragma unroll
    for (int i = 0; i < 2; i++)
#pragma unroll
        for (int j = 0; j < 8; j++)
#pragma unroll
            for (int q = 0; q < 4; q++) c[i][j][q] = 0.f;

    // ldmatrix base addresses (x4 layout):
    // A: lanes 0-15 -> rows (m..m+15) at k0 ; lanes 16-31 -> same rows at k0+8
    const int arow = wm * 32 + (lane & 15);
    const int acol = (lane >> 4) * 8;
    // B: lanes 0-7 rows n..n+7 @k0; 8-15 same rows @k0+8; 16-23 rows n+8..15 @k0; 24-31 @k0+8
    const int brow = wn * 64 + ((lane >> 4) << 3) + (lane & 7);
    const int bcol = ((lane >> 3) & 1) * 8;

    const uint32_t aAh = smem_u32(&sA[0][arow][acol]);
    const uint32_t aAl = smem_u32(&sA[1][arow][acol]);
    const uint32_t aBh = smem_u32(&sB[0][brow][bcol]);
    const uint32_t aBl = smem_u32(&sB[1][brow][bcol]);

    for (int k0 = 0; k0 < K; k0 += 32) {
        if (k0) __syncthreads();
        // load 4 tiles: 128 rows x 32 bf16 each = 512 float4 per tile
#pragma unroll
        for (int i = 0; i < 2; i++) {
            const int idx = i * 256 + tid;          // 0..511
            const int r  = idx >> 2;
            const int cc = idx & 3;
            const size_t offA = (size_t)(m0 + r) * K + k0 + cc * 8;
            const size_t offB = (size_t)(n0 + r) * K + k0 + cc * 8;
            *(float4*)&sA[0][r][cc * 8] = *(const float4*)(Ah + offA);
            *(float4*)&sA[1][r][cc * 8] = *(const float4*)(Al + offA);
            *(float4*)&sB[0][r][cc * 8] = *(const float4*)(Bh + offB);
            *(float4*)&sB[1][r][cc * 8] = *(const float4*)(Bl + offB);
        }
        __syncthreads();

#pragma unroll
        for (int ks = 0; ks < 2; ks++) {
            const uint32_t koffB = (uint32_t)(ks * 16 * 2);   // bytes
            uint32_t ah[2][4], al[2][4];
#pragma unroll
            for (int mt = 0; mt < 2; mt++) {
                const uint32_t moff = (uint32_t)((mt * 16 * PADW + ks * 16) * 2);
                ldsm_x4(ah[mt], aAh + moff);
                ldsm_x4(al[mt], aAl + moff);
            }
#pragma unroll
            for (int nt = 0; nt < 4; nt++) {
                uint32_t bh[4], bl[4];
                const uint32_t noff = (uint32_t)(nt * 16 * PADW * 2) + koffB;
                ldsm_x4(bh, aBh + noff);
                ldsm_x4(bl, aBl + noff);
#pragma unroll
                for (int mt = 0; mt < 2; mt++)
#pragma unroll
                    for (int j = 0; j < 2; j++) {
                        float* cr = c[mt][nt * 2 + j];
                        mma16816(cr, ah[mt], &bh[j * 2]);
                        mma16816(cr, ah[mt], &bl[j * 2]);
                        mma16816(cr, al[mt], &bh[j * 2]);
                    }
            }
        }
    }

    // epilogue: c frag lane mapping: (row = lane/4 [+8], col = 2*(lane%3..) )
#pragma unroll
    for (int mt = 0; mt < 2; mt++) {
        const int mrow = m0 + wm * 32 + mt * 16 + (lane >> 2);
#pragma unroll
        for (int n8 = 0; n8 < 8; n8++) {
            const int ncol = n0 + wn * 64 + n8 * 8 + 2 * (lane & 3);
            float2 bb = *(const float2*)(bias + ncol);
            float2 o0, o1;
            o0.x = c[mt][n8][0] + bb.x; o0.y = c[mt][n8][1] + bb.y;
            o1.x = c[mt][n8][2] + bb.x; o1.y = c[mt][n8][3] + bb.y;
            *(float2*)&C[(size_t)mrow * N + ncol]       = o0;
            *(float2*)&C[(size_t)(mrow + 8) * N + ncol] = o1;
        }
    }
}

// ---------------------------------------------------------------------------
// Kernel: RoPE + scatter qkv -> q/k/v in [B,H,L,Dh] layout.
// ---------------------------------------------------------------------------
__global__ __launch_bounds__(256)
void rope_scatter(const float* __restrict__ qkv,
                  float* __restrict__ Qo, float* __restrict__ Ko, float* __restrict__ Vo)
{
    int idx = blockIdx.x * blockDim.x + threadIdx.x;
    const int total = Bb * Ll * Hh * (DhD / 2);
    if (idx >= total) return;

    const int j = idx & 31;
    int t = idx >> 5;
    const int h = t & (Hh - 1);
    t >>= 4;
    const int l = t & (Ll - 1);
    const int b = t >> 11;

    const int m = b * Ll + l;
    const float2* row = (const float2*)(qkv + (size_t)m * QKVN);
    const int p = h * 32 + j;

    float2 q2 = row[p];
    float2 k2 = row[512 + p];
    float2 v2 = row[1024 + p];

    const float inv_freq = __expf(-(float)j * (9.210340371976184f / 32.0f));
    const float fr = (float)l * inv_freq;
    float s, c;
    sincosf(fr, &s, &c);

    float2 qo, ko;
    qo.x = q2.x * c - q2.y * s;
    qo.y = q2.x * s + q2.y * c;
    ko.x = k2.x * c - k2.y * s;
    ko.y = k2.x * s + k2.y * c;

    const size_t base = ((size_t)(b * Hh + h) * Ll + l) * (DhD / 2) + j;
    ((float2*)Qo)[base] = qo;
    ((float2*)Ko)[base] = ko;
    ((float2*)Vo)[base] = v2;
}

// ---------------------------------------------------------------------------
// Kernel: attention, inverted mask: allowed(q,k) = (k > q) || (k >= PAD)
// (unchanged from R3 — tensorize next round)
// ---------------------------------------------------------------------------
#define BQ 128
#define TK 16

__global__ __launch_bounds__(BQ)
void attn_kernel(const float* __restrict__ Q, const float* __restrict__ K,
                 const float* __restrict__ V, float* __restrict__ Out)
{
    const int bh  = blockIdx.x;
    const int q0  = blockIdx.y * BQ;
    const int tid = threadIdx.x;
    const int qi  = q0 + tid;

    __shared__ float Ks[TK][DhD];
    __shared__ float Vs[TK][DhD];

    float4 qf[DhD / 4];
    {
        const float4* qp = (const float4*)(Q + ((size_t)bh * Ll + qi) * DhD);
#pragma unroll
        for (int i = 0; i < DhD / 4; i++) qf[i] = qp[i];
    }

    float acc[DhD];
#pragma unroll
    for (int d = 0; d < DhD; d++) acc[d] = 0.f;
    float mi = -1e30f, li = 0.f;

    const float4* Kg = (const float4*)(K + (size_t)bh * Ll * DhD);
    const float4* Vg = (const float4*)(V + (size_t)bh * Ll * DhD);

    for (int kt = 0; kt < Ll; kt += TK) {
        const int klast = kt + TK - 1;
        if (klast <= q0 && klast < PAD) continue;

#pragma unroll
        for (int t = 0; t < 2; t++) {
            int vidx = t * BQ + tid;
            ((float4*)Ks)[vidx] = Kg[(size_t)kt * (DhD / 4) + vidx];
            ((float4*)Vs)[vidx] = Vg[(size_t)kt * (DhD / 4) + vidx];
        }
        __syncthreads();

        if (klast > qi || klast >= PAD) {
            float s[TK];
#pragma unroll
            for (int j = 0; j < TK; j++) s[j] = 0.f;
#pragma unroll 4
            for (int i = 0; i < DhD / 4; i++) {
                float4 qv = qf[i];
#pragma unroll
                for (int j = 0; j < TK; j++) {
                    float4 kv = *(const float4*)&Ks[j][i * 4];
                    s[j] = fmaf(qv.x, kv.x, s[j]);
                    s[j] = fmaf(qv.y, kv.y, s[j]);
                    s[j] = fmaf(qv.z, kv.z, s[j]);
                    s[j] = fmaf(qv.w, kv.w, s[j]);
                }
            }
            float tmax = -1e30f;
#pragma unroll
            for (int j = 0; j < TK; j++) {
                const int kg = kt + j;
                const bool ok = (kg > qi) || (kg >= PAD);
                s[j] = ok ? s[j] * 0.125f : -1e30f;
                tmax = fmaxf(tmax, s[j]);
            }
            const float newm = fmaxf(mi, tmax);
            const float alpha = __expf(mi - newm);
            li *= alpha;
#pragma unroll
            for (int d = 0; d < DhD; d++) acc[d] *= alpha;
            mi = newm;
#pragma unroll 2
            for (int j = 0; j < TK; j++) {
                const float p = __expf(s[j] - newm);
                li += p;
#pragma unroll
                for (int i = 0; i < DhD / 4; i++) {
                    float4 vv = *(const float4*)&Vs[j][i * 4];
                    acc[4 * i + 0] = fmaf(p, vv.x, acc[4 * i + 0]);
                    acc[4 * i + 1] = fmaf(p, vv.y, acc[4 * i + 1]);
                    acc[4 * i + 2] = fmaf(p, vv.z, acc[4 * i + 2]);
                    acc[4 * i + 3] = fmaf(p, vv.w, acc[4 * i + 3]);
                }
            }
        }
        __syncthreads();
    }

    const int b = bh >> 4;
    const int h = bh & (Hh - 1);
    const float inv = 1.f / li;
    float4* op = (float4*)(Out + ((size_t)(b * Ll + qi) * Dm) + h * DhD);
#pragma unroll
    for (int i = 0; i < DhD / 4; i++) {
        float4 o;
        o.x = acc[4 * i + 0] * inv; o.y = acc[4 * i + 1] * inv;
        o.z = acc[4 * i + 2] * inv; o.w = acc[4 * i + 3] * inv;
        op[i] = o;
    }
}

// ---------------------------------------------------------------------------
// Launch
// Inputs (metadata order): x, pad_mask, Wqkv, bqkv, Wout, bout
// ---------------------------------------------------------------------------
extern "C" void kernel_launch(void* const* d_in, const int* in_sizes, int n_in,
                              void* d_out, int out_size)
{
    const float* x    = (const float*)d_in[0];
    const float* Wqkv = (const float*)d_in[2];
    const float* bqkv = (const float*)d_in[3];
    const float* Wout = (const float*)d_in[4];
    const float* bout = (const float*)d_in[5];
    float* out = (float*)d_out;

    float *qkv, *qb, *kb, *vb, *attn;
    __nv_bfloat16 *ah, *al, *bh, *bl;
    cudaGetSymbolAddress((void**)&qkv,  g_qkv);
    cudaGetSymbolAddress((void**)&qb,   g_q);
    cudaGetSymbolAddress((void**)&kb,   g_k);
    cudaGetSymbolAddress((void**)&vb,   g_v);
    cudaGetSymbolAddress((void**)&attn, g_attn);
    cudaGetSymbolAddress((void**)&ah,   g_ah);
    cudaGetSymbolAddress((void**)&al,   g_al);
    cudaGetSymbolAddress((void**)&bh,   g_bh);
    cudaGetSymbolAddress((void**)&bl,   g_bl);

    // 1) split x and Wqkv into bf16 hi/lo
    {
        int n2 = (Mrows * Dm) / 2;
        split_bf16<<<(n2 + 255) / 256, 256>>>(x, ah, al, n2);
        n2 = (QKVN * Dm) / 2;
        split_bf16<<<(n2 + 255) / 256, 256>>>(Wqkv, bh, bl, n2);
    }
    // 2) QKV projection + bias (tensor cores via mma.sync)
    {
        dim3 grid(QKVN / 128, Mrows / 128);
        gemm_mma_split<<<grid, 256>>>(ah, al, bh, bl, bqkv, qkv, Mrows, QKVN, Dm);
    }
    // 3) RoPE + scatter
    {
        int total = Bb * Ll * Hh * (DhD / 2);
        rope_scatter<<<(total + 255) / 256, 256>>>(qkv, qb, kb, vb);
    }
    // 4) attention
    {
        dim3 grid(Bb * Hh, Ll / BQ);
        attn_kernel<<<grid, BQ>>>(qb, kb, vb, attn);
    }
    // 5) split attn output and Wout (reuse buffers)
    {
        int n2 = (Mrows * Dm) / 2;
        split_bf16<<<(n2 + 255) / 256, 256>>>(attn, ah, al, n2);
        n2 = (Dm * Dm) / 2;
        split_bf16<<<(n2 + 255) / 256, 256>>>(Wout, bh, bl, n2);
    }
    // 6) output projection + bias (tensor cores via mma.sync)
    {
        dim3 grid(Dm / 128, Mrows / 128);
        gemm_mma_split<<<grid, 256>>>(ah, al, bh, bl, bout, out, Mrows, Dm, Dm);
    }
}

// round 7
// speedup vs baseline: 1.6241x; 1.6241x over previous
#include <cuda_runtime.h>
#include <cuda_bf16.h>
#include <cstdint>
#include <math.h>

// Problem constants (fixed by the dataset)
#define Bb   2
#define Ll   2048
#define Dm   1024
#define Hh   16
#define DhD  64
#define PAD  1536
#define Mrows (Bb * Ll)          // 4096
#define QKVN  (3 * Dm)           // 3072

// ---------------------------------------------------------------------------
// Scratch (device globals; no runtime allocation allowed)
// ---------------------------------------------------------------------------
__device__ float g_qkv[(size_t)Mrows * QKVN];         // 4096 x 3072
__device__ float g_q[(size_t)Bb * Hh * Ll * DhD];     // [B,H,L,Dh]
__device__ float g_k[(size_t)Bb * Hh * Ll * DhD];
__device__ float g_v[(size_t)Bb * Hh * Ll * DhD];
__device__ float g_attn[(size_t)Mrows * Dm];          // [B,L,H*Dh]
// bf16 split buffers (A reused for x then attn; B reused for Wqkv then Wout)
__device__ __nv_bfloat16 g_ah[(size_t)Mrows * Dm];
__device__ __nv_bfloat16 g_al[(size_t)Mrows * Dm];
__device__ __nv_bfloat16 g_bh[(size_t)QKVN * Dm];
__device__ __nv_bfloat16 g_bl[(size_t)QKVN * Dm];

// ---------------------------------------------------------------------------
// mma.sync helpers (baseline PTX features, compile for compute_103)
// ---------------------------------------------------------------------------
__device__ __forceinline__ uint32_t smem_u32(const void* p) {
    uint32_t a;
    asm("{ .reg .u64 t; cvta.to.shared.u64 t, %1; cvt.u32.u64 %0, t; }" : "=r"(a) : "l"(p));
    return a;
}
__device__ __forceinline__ void ldsm_x4(uint32_t r[4], uint32_t addr) {
    asm volatile("ldmatrix.sync.aligned.m8n8.x4.shared.b16 {%0,%1,%2,%3}, [%4];"
                 : "=r"(r[0]), "=r"(r[1]), "=r"(r[2]), "=r"(r[3]) : "r"(addr));
}
// non-volatile: register-only op, let the compiler schedule/interleave chains
__device__ __forceinline__ void mma16816(float c[4], const uint32_t a[4], const uint32_t b[2]) {
    asm("mma.sync.aligned.m16n8k16.row.col.f32.bf16.bf16.f32 "
        "{%0,%1,%2,%3}, {%4,%5,%6,%7}, {%8,%9}, {%0,%1,%2,%3};"
        : "+f"(c[0]), "+f"(c[1]), "+f"(c[2]), "+f"(c[3])
        : "r"(a[0]), "r"(a[1]), "r"(a[2]), "r"(a[3]), "r"(b[0]), "r"(b[1]));
}
__device__ __forceinline__ void cpa16(uint32_t dst, const void* src) {
    asm volatile("cp.async.cg.shared.global [%0], [%1], 16;" :: "r"(dst), "l"(src));
}

// ---------------------------------------------------------------------------
// Kernel: fp32 -> (bf16 hi, bf16 lo) split, 2 elements/thread
// ---------------------------------------------------------------------------
__global__ __launch_bounds__(256)
void split_bf16(const float* __restrict__ X, __nv_bfloat16* __restrict__ H,
                __nv_bfloat16* __restrict__ Lo, int n2)
{
    int i = blockIdx.x * blockDim.x + threadIdx.x;
    if (i >= n2) return;
    float2 x = ((const float2*)X)[i];
    __nv_bfloat16 h0 = __float2bfloat16(x.x);
    __nv_bfloat16 h1 = __float2bfloat16(x.y);
    __nv_bfloat162 hv; hv.x = h0; hv.y = h1;
    __nv_bfloat162 lv;
    lv.x = __float2bfloat16(x.x - __bfloat162float(h0));
    lv.y = __float2bfloat16(x.y - __bfloat162float(h1));
    ((__nv_bfloat162*)H)[i]  = hv;
    ((__nv_bfloat162*)Lo)[i] = lv;
}

// ---------------------------------------------------------------------------
// mma.sync bf16-split GEMM: C[M,N] = (Ah+Al)[M,K] * (Bh+Bl)[N,K]^T + bias
//   = Ah*Bh + Ah*Bl + Al*Bh  (Al*Bl dropped, ~2^-18 relative)
// 128x128 CTA tile, 8 warps (4x2), 32x64 warp tile, K-chunk 32.
// cp.async double-buffered (2 stages x 40KB dynamic smem), 2 CTAs/SM.
// Rows padded to 40 bf16 (80B): 80*r mod 128 hits 8 distinct 16B slots
// -> conflict-free ldmatrix.
// ---------------------------------------------------------------------------
#define PADW 40
#define KC   32
#define TILE_BYTES (128 * PADW * 2)      // 10240
#define STAGE_BYTES (4 * TILE_BYTES)     // 40960
#define GSMEM (2 * STAGE_BYTES)          // 81920

__global__ __launch_bounds__(256, 2)
void gemm_mma_split(const __nv_bfloat16* __restrict__ Ah, const __nv_bfloat16* __restrict__ Al,
                    const __nv_bfloat16* __restrict__ Bh, const __nv_bfloat16* __restrict__ Bl,
                    const float* __restrict__ bias, float* __restrict__ C,
                    int M, int N, int K)
{
    extern __shared__ char dsm[];
    const uint32_t sbase = smem_u32(dsm);

    const int tid  = threadIdx.x;
    const int lane = tid & 31;
    const int wid  = tid >> 5;
    const int wm   = wid & 3;        // 0..3 (m)
    const int wn   = wid >> 2;       // 0..1 (n)
    const int m0   = blockIdx.y * 128;
    const int n0   = blockIdx.x * 128;

    float c[2][8][4];
#pragma unroll
    for (int i = 0; i < 2; i++)
#pragma unroll
        for (int j = 0; j < 8; j++)
#pragma unroll
            for (int q = 0; q < 4; q++) c[i][j][q] = 0.f;

    // global source rows for this thread's cp.asyncs
    const int lr  = tid >> 2;        // 0..63  (row, first half)
    const int lcc = (tid & 3) * 8;   // bf16 col within 32-wide chunk
    const __nv_bfloat16* srcs[4] = {
        Ah + (size_t)(m0 + lr) * K + lcc,  Al + (size_t)(m0 + lr) * K + lcc,
        Bh + (size_t)(n0 + lr) * K + lcc,  Bl + (size_t)(n0 + lr) * K + lcc };
    const size_t rowskip = (size_t)64 * K;             // second 64 rows
    const uint32_t dst0 = sbase + (uint32_t)(lr * PADW + lcc) * 2;
    const uint32_t dst1 = dst0 + (uint32_t)(64 * PADW) * 2;

    // ldmatrix base addresses (stage 0):
    const int arow = wm * 32 + (lane & 15);
    const int acol = (lane >> 4) * 8;
    const int brow = wn * 64 + ((lane >> 4) << 3) + (lane & 7);
    const int bcol = ((lane >> 3) & 1) * 8;
    const uint32_t aAh = sbase + 0 * TILE_BYTES + (uint32_t)(arow * PADW + acol) * 2;
    const uint32_t aAl = sbase + 1 * TILE_BYTES + (uint32_t)(arow * PADW + acol) * 2;
    const uint32_t aBh = sbase + 2 * TILE_BYTES + (uint32_t)(brow * PADW + bcol) * 2;
    const uint32_t aBl = sbase + 3 * TILE_BYTES + (uint32_t)(brow * PADW + bcol) * 2;

    const int nch = K / KC;          // 32

    // prologue: load stage 0
#pragma unroll
    for (int t = 0; t < 4; t++) {
        const uint32_t toff = t * TILE_BYTES;
        cpa16(dst0 + toff, srcs[t]);
        cpa16(dst1 + toff, srcs[t] + rowskip);
    }
    asm volatile("cp.async.commit_group;");

    for (int s = 0; s < nch; s++) {
        // issue loads for next chunk into the other buffer
        if (s + 1 < nch) {
            const uint32_t stoff = ((s + 1) & 1) * (uint32_t)STAGE_BYTES;
            const int koff = (s + 1) * KC;
#pragma unroll
            for (int t = 0; t < 4; t++) {
                const uint32_t toff = stoff + t * TILE_BYTES;
                cpa16(dst0 + toff, srcs[t] + koff);
                cpa16(dst1 + toff, srcs[t] + koff + rowskip);
            }
            asm volatile("cp.async.commit_group;");
            asm volatile("cp.async.wait_group 1;");
        } else {
            asm volatile("cp.async.wait_group 0;");
        }
        __syncthreads();

        const uint32_t stoff = (s & 1) * (uint32_t)STAGE_BYTES;
#pragma unroll
        for (int ks = 0; ks < 2; ks++) {
            const uint32_t kb = (uint32_t)(ks * 16 * 2);   // byte offset in k
            uint32_t ahf[2][4], alf[2][4];
#pragma unroll
            for (int mt = 0; mt < 2; mt++) {
                const uint32_t moff = stoff + (uint32_t)(mt * 16 * PADW * 2) + kb;
                ldsm_x4(ahf[mt], aAh + moff);
                ldsm_x4(alf[mt], aAl + moff);
            }
#pragma unroll
            for (int nt = 0; nt < 4; nt++) {
                uint32_t bhf[4], blf[4];
                const uint32_t noff = stoff + (uint32_t)(nt * 16 * PADW * 2) + kb;
                ldsm_x4(bhf, aBh + noff);
                ldsm_x4(blf, aBl + noff);
                // pass 1: ah x bh (4 independent accumulators)
                mma16816(c[0][nt * 2 + 0], ahf[0], &bhf[0]);
                mma16816(c[0][nt * 2 + 1], ahf[0], &bhf[2]);
                mma16816(c[1][nt * 2 + 0], ahf[1], &bhf[0]);
                mma16816(c[1][nt * 2 + 1], ahf[1], &bhf[2]);
                // pass 2: ah x bl
                mma16816(c[0][nt * 2 + 0], ahf[0], &blf[0]);
                mma16816(c[0][nt * 2 + 1], ahf[0], &blf[2]);
                mma16816(c[1][nt * 2 + 0], ahf[1], &blf[0]);
                mma16816(c[1][nt * 2 + 1], ahf[1], &blf[2]);
                // pass 3: al x bh
                mma16816(c[0][nt * 2 + 0], alf[0], &bhf[0]);
                mma16816(c[0][nt * 2 + 1], alf[0], &bhf[2]);
                mma16816(c[1][nt * 2 + 0], alf[1], &bhf[0]);
                mma16816(c[1][nt * 2 + 1], alf[1], &bhf[2]);
            }
        }
        __syncthreads();
    }

    // epilogue: frag mapping row = lane/4 (+8), col = 2*(lane%4)
#pragma unroll
    for (int mt = 0; mt < 2; mt++) {
        const int mrow = m0 + wm * 32 + mt * 16 + (lane >> 2);
#pragma unroll
        for (int n8 = 0; n8 < 8; n8++) {
            const int ncol = n0 + wn * 64 + n8 * 8 + 2 * (lane & 3);
            float2 bb = *(const float2*)(bias + ncol);
            float2 o0, o1;
            o0.x = c[mt][n8][0] + bb.x; o0.y = c[mt][n8][1] + bb.y;
            o1.x = c[mt][n8][2] + bb.x; o1.y = c[mt][n8][3] + bb.y;
            *(float2*)&C[(size_t)mrow * N + ncol]       = o0;
            *(float2*)&C[(size_t)(mrow + 8) * N + ncol] = o1;
        }
    }
}

// ---------------------------------------------------------------------------
// Kernel: RoPE + scatter qkv -> q/k/v in [B,H,L,Dh] layout.
// ---------------------------------------------------------------------------
__global__ __launch_bounds__(256)
void rope_scatter(const float* __restrict__ qkv,
                  float* __restrict__ Qo, float* __restrict__ Ko, float* __restrict__ Vo)
{
    int idx = blockIdx.x * blockDim.x + threadIdx.x;
    const int total = Bb * Ll * Hh * (DhD / 2);
    if (idx >= total) return;

    const int j = idx & 31;
    int t = idx >> 5;
    const int h = t & (Hh - 1);
    t >>= 4;
    const int l = t & (Ll - 1);
    const int b = t >> 11;

    const int m = b * Ll + l;
    const float2* row = (const float2*)(qkv + (size_t)m * QKVN);
    const int p = h * 32 + j;

    float2 q2 = row[p];
    float2 k2 = row[512 + p];
    float2 v2 = row[1024 + p];

    const float inv_freq = __expf(-(float)j * (9.210340371976184f / 32.0f));
    const float fr = (float)l * inv_freq;
    float s, c;
    sincosf(fr, &s, &c);

    float2 qo, ko;
    qo.x = q2.x * c - q2.y * s;
    qo.y = q2.x * s + q2.y * c;
    ko.x = k2.x * c - k2.y * s;
    ko.y = k2.x * s + k2.y * c;

    const size_t base = ((size_t)(b * Hh + h) * Ll + l) * (DhD / 2) + j;
    ((float2*)Qo)[base] = qo;
    ((float2*)Ko)[base] = ko;
    ((float2*)Vo)[base] = v2;
}

// ---------------------------------------------------------------------------
// Kernel: attention, inverted mask: allowed(q,k) = (k > q) || (k >= PAD)
// (unchanged — proven ~750us; tensorize after GEMM path is validated)
// ---------------------------------------------------------------------------
#define BQ 128
#define TK 16

__global__ __launch_bounds__(BQ)
void attn_kernel(const float* __restrict__ Q, const float* __restrict__ K,
                 const float* __restrict__ V, float* __restrict__ Out)
{
    const int bh  = blockIdx.x;
    const int q0  = blockIdx.y * BQ;
    const int tid = threadIdx.x;
    const int qi  = q0 + tid;

    __shared__ float Ks[TK][DhD];
    __shared__ float Vs[TK][DhD];

    float4 qf[DhD / 4];
    {
        const float4* qp = (const float4*)(Q + ((size_t)bh * Ll + qi) * DhD);
#pragma unroll
        for (int i = 0; i < DhD / 4; i++) qf[i] = qp[i];
    }

    float acc[DhD];
#pragma unroll
    for (int d = 0; d < DhD; d++) acc[d] = 0.f;
    float mi = -1e30f, li = 0.f;

    const float4* Kg = (const float4*)(K + (size_t)bh * Ll * DhD);
    const float4* Vg = (const float4*)(V + (size_t)bh * Ll * DhD);

    for (int kt = 0; kt < Ll; kt += TK) {
        const int klast = kt + TK - 1;
        if (klast <= q0 && klast < PAD) continue;

#pragma unroll
        for (int t = 0; t < 2; t++) {
            int vidx = t * BQ + tid;
            ((float4*)Ks)[vidx] = Kg[(size_t)kt * (DhD / 4) + vidx];
            ((float4*)Vs)[vidx] = Vg[(size_t)kt * (DhD / 4) + vidx];
        }
        __syncthreads();

        if (klast > qi || klast >= PAD) {
            float s[TK];
#pragma unroll
            for (int j = 0; j < TK; j++) s[j] = 0.f;
#pragma unroll 4
            for (int i = 0; i < DhD / 4; i++) {
                float4 qv = qf[i];
#pragma unroll
                for (int j = 0; j < TK; j++) {
                    float4 kv = *(const float4*)&Ks[j][i * 4];
                    s[j] = fmaf(qv.x, kv.x, s[j]);
                    s[j] = fmaf(qv.y, kv.y, s[j]);
                    s[j] = fmaf(qv.z, kv.z, s[j]);
                    s[j] = fmaf(qv.w, kv.w, s[j]);
                }
            }
            float tmax = -1e30f;
#pragma unroll
            for (int j = 0; j < TK; j++) {
                const int kg = kt + j;
                const bool ok = (kg > qi) || (kg >= PAD);
                s[j] = ok ? s[j] * 0.125f : -1e30f;
                tmax = fmaxf(tmax, s[j]);
            }
            const float newm = fmaxf(mi, tmax);
            const float alpha = __expf(mi - newm);
            li *= alpha;
#pragma unroll
            for (int d = 0; d < DhD; d++) acc[d] *= alpha;
            mi = newm;
#pragma unroll 2
            for (int j = 0; j < TK; j++) {
                const float p = __expf(s[j] - newm);
                li += p;
#pragma unroll
                for (int i = 0; i < DhD / 4; i++) {
                    float4 vv = *(const float4*)&Vs[j][i * 4];
                    acc[4 * i + 0] = fmaf(p, vv.x, acc[4 * i + 0]);
                    acc[4 * i + 1] = fmaf(p, vv.y, acc[4 * i + 1]);
                    acc[4 * i + 2] = fmaf(p, vv.z, acc[4 * i + 2]);
                    acc[4 * i + 3] = fmaf(p, vv.w, acc[4 * i + 3]);
                }
            }
        }
        __syncthreads();
    }

    const int b = bh >> 4;
    const int h = bh & (Hh - 1);
    const float inv = 1.f / li;
    float4* op = (float4*)(Out + ((size_t)(b * Ll + qi) * Dm) + h * DhD);
#pragma unroll
    for (int i = 0; i < DhD / 4; i++) {
        float4 o;
        o.x = acc[4 * i + 0] * inv; o.y = acc[4 * i + 1] * inv;
        o.z = acc[4 * i + 2] * inv; o.w = acc[4 * i + 3] * inv;
        op[i] = o;
    }
}

// ---------------------------------------------------------------------------
// Launch
// Inputs (metadata order): x, pad_mask, Wqkv, bqkv, Wout, bout
// ---------------------------------------------------------------------------
extern "C" void kernel_launch(void* const* d_in, const int* in_sizes, int n_in,
                              void* d_out, int out_size)
{
    const float* x    = (const float*)d_in[0];
    const float* Wqkv = (const float*)d_in[2];
    const float* bqkv = (const float*)d_in[3];
    const float* Wout = (const float*)d_in[4];
    const float* bout = (const float*)d_in[5];
    float* out = (float*)d_out;

    float *qkv, *qb, *kb, *vb, *attn;
    __nv_bfloat16 *ah, *al, *bh, *bl;
    cudaGetSymbolAddress((void**)&qkv,  g_qkv);
    cudaGetSymbolAddress((void**)&qb,   g_q);
    cudaGetSymbolAddress((void**)&kb,   g_k);
    cudaGetSymbolAddress((void**)&vb,   g_v);
    cudaGetSymbolAddress((void**)&attn, g_attn);
    cudaGetSymbolAddress((void**)&ah,   g_ah);
    cudaGetSymbolAddress((void**)&al,   g_al);
    cudaGetSymbolAddress((void**)&bh,   g_bh);
    cudaGetSymbolAddress((void**)&bl,   g_bl);

    cudaFuncSetAttribute(gemm_mma_split, cudaFuncAttributeMaxDynamicSharedMemorySize, GSMEM);

    // 1) split x and Wqkv into bf16 hi/lo
    {
        int n2 = (Mrows * Dm) / 2;
        split_bf16<<<(n2 + 255) / 256, 256>>>(x, ah, al, n2);
        n2 = (QKVN * Dm) / 2;
        split_bf16<<<(n2 + 255) / 256, 256>>>(Wqkv, bh, bl, n2);
    }
    // 2) QKV projection + bias (tensor cores via mma.sync)
    {
        dim3 grid(QKVN / 128, Mrows / 128);
        gemm_mma_split<<<grid, 256, GSMEM>>>(ah, al, bh, bl, bqkv, qkv, Mrows, QKVN, Dm);
    }
    // 3) RoPE + scatter
    {
        int total = Bb * Ll * Hh * (DhD / 2);
        rope_scatter<<<(total + 255) / 256, 256>>>(qkv, qb, kb, vb);
    }
    // 4) attention
    {
        dim3 grid(Bb * Hh, Ll / BQ);
        attn_kernel<<<grid, BQ>>>(qb, kb, vb, attn);
    }
    // 5) split attn output and Wout (reuse buffers)
    {
        int n2 = (Mrows * Dm) / 2;
        split_bf16<<<(n2 + 255) / 256, 256>>>(attn, ah, al, n2);
        n2 = (Dm * Dm) / 2;
        split_bf16<<<(n2 + 255) / 256, 256>>>(Wout, bh, bl, n2);
    }
    // 6) output projection + bias (tensor cores via mma.sync)
    {
        dim3 grid(Dm / 128, Mrows / 128);
        gemm_mma_split<<<grid, 256, GSMEM>>>(ah, al, bh, bl, bout, out, Mrows, Dm, Dm);
    }
}

// round 8
// speedup vs baseline: 3.5000x; 2.1550x over previous
#include <cuda_runtime.h>
#include <cuda_bf16.h>
#include <cstdint>
#include <math.h>

// Problem constants (fixed by the dataset)
#define Bb   2
#define Ll   2048
#define Dm   1024
#define Hh   16
#define DhD  64
#define PAD  1536
#define Mrows (Bb * Ll)          // 4096
#define QKVN  (3 * Dm)           // 3072

// ---------------------------------------------------------------------------
// Scratch (device globals; no runtime allocation allowed)
// ---------------------------------------------------------------------------
__device__ float g_qkv[(size_t)Mrows * QKVN];         // 4096 x 3072
__device__ float g_attn[(size_t)Mrows * Dm];          // [B,L,H*Dh]
// bf16 split buffers for GEMMs (A reused for x then attn; B for Wqkv/Wout)
__device__ __nv_bfloat16 g_ah[(size_t)Mrows * Dm];
__device__ __nv_bfloat16 g_al[(size_t)Mrows * Dm];
__device__ __nv_bfloat16 g_bh[(size_t)QKVN * Dm];
__device__ __nv_bfloat16 g_bl[(size_t)QKVN * Dm];
// bf16 hi/lo q/k/v in [B*H][L][64] layout (q pre-scaled by 1/8)
#define QKVSZ ((size_t)Bb * Hh * Ll * DhD)
__device__ __nv_bfloat16 g_qh[QKVSZ], g_ql[QKVSZ];
__device__ __nv_bfloat16 g_kh[QKVSZ], g_kl[QKVSZ];
__device__ __nv_bfloat16 g_vh[QKVSZ], g_vl[QKVSZ];

// ---------------------------------------------------------------------------
// mma.sync helpers (baseline PTX features, compile for compute_103)
// ---------------------------------------------------------------------------
__device__ __forceinline__ uint32_t smem_u32(const void* p) {
    uint32_t a;
    asm("{ .reg .u64 t; cvta.to.shared.u64 t, %1; cvt.u32.u64 %0, t; }" : "=r"(a) : "l"(p));
    return a;
}
__device__ __forceinline__ void ldsm_x4(uint32_t r[4], uint32_t addr) {
    asm volatile("ldmatrix.sync.aligned.m8n8.x4.shared.b16 {%0,%1,%2,%3}, [%4];"
                 : "=r"(r[0]), "=r"(r[1]), "=r"(r[2]), "=r"(r[3]) : "r"(addr));
}
__device__ __forceinline__ void ldsm_x4_t(uint32_t r[4], uint32_t addr) {
    asm volatile("ldmatrix.sync.aligned.m8n8.x4.trans.shared.b16 {%0,%1,%2,%3}, [%4];"
                 : "=r"(r[0]), "=r"(r[1]), "=r"(r[2]), "=r"(r[3]) : "r"(addr));
}
__device__ __forceinline__ void mma16816(float c[4], const uint32_t a[4], const uint32_t b[2]) {
    asm("mma.sync.aligned.m16n8k16.row.col.f32.bf16.bf16.f32 "
        "{%0,%1,%2,%3}, {%4,%5,%6,%7}, {%8,%9}, {%0,%1,%2,%3};"
        : "+f"(c[0]), "+f"(c[1]), "+f"(c[2]), "+f"(c[3])
        : "r"(a[0]), "r"(a[1]), "r"(a[2]), "r"(a[3]), "r"(b[0]), "r"(b[1]));
}
__device__ __forceinline__ void cpa16(uint32_t dst, const void* src) {
    asm volatile("cp.async.cg.shared.global [%0], [%1], 16;" :: "r"(dst), "l"(src));
}
__device__ __forceinline__ uint32_t packbf(float lo, float hi) {
    uint32_t r;
    asm("cvt.rn.bf16x2.f32 %0, %1, %2;" : "=r"(r) : "f"(hi), "f"(lo));
    return r;
}

// ---------------------------------------------------------------------------
// Kernel: fp32 -> (bf16 hi, bf16 lo) split, 2 elements/thread
// ---------------------------------------------------------------------------
__global__ __launch_bounds__(256)
void split_bf16(const float* __restrict__ X, __nv_bfloat16* __restrict__ H,
                __nv_bfloat16* __restrict__ Lo, int n2)
{
    int i = blockIdx.x * blockDim.x + threadIdx.x;
    if (i >= n2) return;
    float2 x = ((const float2*)X)[i];
    __nv_bfloat16 h0 = __float2bfloat16(x.x);
    __nv_bfloat16 h1 = __float2bfloat16(x.y);
    __nv_bfloat162 hv; hv.x = h0; hv.y = h1;
    __nv_bfloat162 lv;
    lv.x = __float2bfloat16(x.x - __bfloat162float(h0));
    lv.y = __float2bfloat16(x.y - __bfloat162float(h1));
    ((__nv_bfloat162*)H)[i]  = hv;
    ((__nv_bfloat162*)Lo)[i] = lv;
}

// ---------------------------------------------------------------------------
// mma.sync bf16-split GEMM (unchanged from R7; ~93% of legacy-HMMA ceiling)
// ---------------------------------------------------------------------------
#define PADW 40
#define KC   32
#define TILE_BYTES (128 * PADW * 2)
#define STAGE_BYTES (4 * TILE_BYTES)
#define GSMEM (2 * STAGE_BYTES)

__global__ __launch_bounds__(256, 2)
void gemm_mma_split(const __nv_bfloat16* __restrict__ Ah, const __nv_bfloat16* __restrict__ Al,
                    const __nv_bfloat16* __restrict__ Bh, const __nv_bfloat16* __restrict__ Bl,
                    const float* __restrict__ bias, float* __restrict__ C,
                    int M, int N, int K)
{
    extern __shared__ char dsm[];
    const uint32_t sbase = smem_u32(dsm);

    const int tid  = threadIdx.x;
    const int lane = tid & 31;
    const int wid  = tid >> 5;
    const int wm   = wid & 3;
    const int wn   = wid >> 2;
    const int m0   = blockIdx.y * 128;
    const int n0   = blockIdx.x * 128;

    float c[2][8][4];
#pragma unroll
    for (int i = 0; i < 2; i++)
#pragma unroll
        for (int j = 0; j < 8; j++)
#pragma unroll
            for (int q = 0; q < 4; q++) c[i][j][q] = 0.f;

    const int lr  = tid >> 2;
    const int lcc = (tid & 3) * 8;
    const __nv_bfloat16* srcs[4] = {
        Ah + (size_t)(m0 + lr) * K + lcc,  Al + (size_t)(m0 + lr) * K + lcc,
        Bh + (size_t)(n0 + lr) * K + lcc,  Bl + (size_t)(n0 + lr) * K + lcc };
    const size_t rowskip = (size_t)64 * K;
    const uint32_t dst0 = sbase + (uint32_t)(lr * PADW + lcc) * 2;
    const uint32_t dst1 = dst0 + (uint32_t)(64 * PADW) * 2;

    const int arow = wm * 32 + (lane & 15);
    const int acol = (lane >> 4) * 8;
    const int brow = wn * 64 + ((lane >> 4) << 3) + (lane & 7);
    const int bcol = ((lane >> 3) & 1) * 8;
    const uint32_t aAh = sbase + 0 * TILE_BYTES + (uint32_t)(arow * PADW + acol) * 2;
    const uint32_t aAl = sbase + 1 * TILE_BYTES + (uint32_t)(arow * PADW + acol) * 2;
    const uint32_t aBh = sbase + 2 * TILE_BYTES + (uint32_t)(brow * PADW + bcol) * 2;
    const uint32_t aBl = sbase + 3 * TILE_BYTES + (uint32_t)(brow * PADW + bcol) * 2;

    const int nch = K / KC;

#pragma unroll
    for (int t = 0; t < 4; t++) {
        const uint32_t toff = t * TILE_BYTES;
        cpa16(dst0 + toff, srcs[t]);
        cpa16(dst1 + toff, srcs[t] + rowskip);
    }
    asm volatile("cp.async.commit_group;");

    for (int s = 0; s < nch; s++) {
        if (s + 1 < nch) {
            const uint32_t stoff = ((s + 1) & 1) * (uint32_t)STAGE_BYTES;
            const int koff = (s + 1) * KC;
#pragma unroll
            for (int t = 0; t < 4; t++) {
                const uint32_t toff = stoff + t * TILE_BYTES;
                cpa16(dst0 + toff, srcs[t] + koff);
                cpa16(dst1 + toff, srcs[t] + koff + rowskip);
            }
            asm volatile("cp.async.commit_group;");
            asm volatile("cp.async.wait_group 1;");
        } else {
            asm volatile("cp.async.wait_group 0;");
        }
        __syncthreads();

        const uint32_t stoff = (s & 1) * (uint32_t)STAGE_BYTES;
#pragma unroll
        for (int ks = 0; ks < 2; ks++) {
            const uint32_t kb = (uint32_t)(ks * 16 * 2);
            uint32_t ahf[2][4], alf[2][4];
#pragma unroll
            for (int mt = 0; mt < 2; mt++) {
                const uint32_t moff = stoff + (uint32_t)(mt * 16 * PADW * 2) + kb;
                ldsm_x4(ahf[mt], aAh + moff);
                ldsm_x4(alf[mt], aAl + moff);
            }
#pragma unroll
            for (int nt = 0; nt < 4; nt++) {
                uint32_t bhf[4], blf[4];
                const uint32_t noff = stoff + (uint32_t)(nt * 16 * PADW * 2) + kb;
                ldsm_x4(bhf, aBh + noff);
                ldsm_x4(blf, aBl + noff);
                mma16816(c[0][nt * 2 + 0], ahf[0], &bhf[0]);
                mma16816(c[0][nt * 2 + 1], ahf[0], &bhf[2]);
                mma16816(c[1][nt * 2 + 0], ahf[1], &bhf[0]);
                mma16816(c[1][nt * 2 + 1], ahf[1], &bhf[2]);
                mma16816(c[0][nt * 2 + 0], ahf[0], &blf[0]);
                mma16816(c[0][nt * 2 + 1], ahf[0], &blf[2]);
                mma16816(c[1][nt * 2 + 0], ahf[1], &blf[0]);
                mma16816(c[1][nt * 2 + 1], ahf[1], &blf[2]);
                mma16816(c[0][nt * 2 + 0], alf[0], &bhf[0]);
                mma16816(c[0][nt * 2 + 1], alf[0], &bhf[2]);
                mma16816(c[1][nt * 2 + 0], alf[1], &bhf[0]);
                mma16816(c[1][nt * 2 + 1], alf[1], &bhf[2]);
            }
        }
        __syncthreads();
    }

#pragma unroll
    for (int mt = 0; mt < 2; mt++) {
        const int mrow = m0 + wm * 32 + mt * 16 + (lane >> 2);
#pragma unroll
        for (int n8 = 0; n8 < 8; n8++) {
            const int ncol = n0 + wn * 64 + n8 * 8 + 2 * (lane & 3);
            float2 bb = *(const float2*)(bias + ncol);
            float2 o0, o1;
            o0.x = c[mt][n8][0] + bb.x; o0.y = c[mt][n8][1] + bb.y;
            o1.x = c[mt][n8][2] + bb.x; o1.y = c[mt][n8][3] + bb.y;
            *(float2*)&C[(size_t)mrow * N + ncol]       = o0;
            *(float2*)&C[(size_t)(mrow + 8) * N + ncol] = o1;
        }
    }
}

// ---------------------------------------------------------------------------
// Kernel: RoPE + scatter qkv -> bf16 hi/lo q(scaled)/k/v in [B*H][L][64].
// ---------------------------------------------------------------------------
__device__ __forceinline__ void split2(float2 v, __nv_bfloat162& h, __nv_bfloat162& l) {
    h.x = __float2bfloat16(v.x); h.y = __float2bfloat16(v.y);
    l.x = __float2bfloat16(v.x - __bfloat162float(h.x));
    l.y = __float2bfloat16(v.y - __bfloat162float(h.y));
}

__global__ __launch_bounds__(256)
void rope_scatter(const float* __restrict__ qkv,
                  __nv_bfloat16* __restrict__ Qh, __nv_bfloat16* __restrict__ Ql,
                  __nv_bfloat16* __restrict__ Kh, __nv_bfloat16* __restrict__ Kl,
                  __nv_bfloat16* __restrict__ Vh, __nv_bfloat16* __restrict__ Vl)
{
    int idx = blockIdx.x * blockDim.x + threadIdx.x;
    const int total = Bb * Ll * Hh * (DhD / 2);
    if (idx >= total) return;

    const int j = idx & 31;
    int t = idx >> 5;
    const int h = t & (Hh - 1);
    t >>= 4;
    const int l = t & (Ll - 1);
    const int b = t >> 11;

    const int m = b * Ll + l;
    const float2* row = (const float2*)(qkv + (size_t)m * QKVN);
    const int p = h * 32 + j;

    float2 q2 = row[p];
    float2 k2 = row[512 + p];
    float2 v2 = row[1024 + p];

    const float inv_freq = __expf(-(float)j * (9.210340371976184f / 32.0f));
    const float fr = (float)l * inv_freq;
    float s, c;
    sincosf(fr, &s, &c);

    float2 qo, ko;
    qo.x = 0.125f * (q2.x * c - q2.y * s);     // fold softmax scale into q
    qo.y = 0.125f * (q2.x * s + q2.y * c);
    ko.x = k2.x * c - k2.y * s;
    ko.y = k2.x * s + k2.y * c;

    const size_t base = ((size_t)(b * Hh + h) * Ll + l) * 32 + j;   // bf16x2 index
    __nv_bfloat162 hh, ll;
    split2(qo, hh, ll);
    ((__nv_bfloat162*)Qh)[base] = hh; ((__nv_bfloat162*)Ql)[base] = ll;
    split2(ko, hh, ll);
    ((__nv_bfloat162*)Kh)[base] = hh; ((__nv_bfloat162*)Kl)[base] = ll;
    split2(v2, hh, ll);
    ((__nv_bfloat162*)Vh)[base] = hh; ((__nv_bfloat162*)Vl)[base] = ll;
}

// ---------------------------------------------------------------------------
// Flash attention with mma.sync bf16-split. Inverted mask:
//   allowed(q,k) = (k > q) || (k >= PAD)
// CTA = 64 queries (4 warps x 16 rows), K/V tiles of 64 keys, cp.async
// double-buffered. Processed tiles are contiguous: j in [min(qt,24), 32).
// Only the diagonal tile (kt == q0, kt < PAD) needs per-element masking.
// ---------------------------------------------------------------------------
#define QSTR 72                        // padded smem row stride (bf16)
#define ATILE_B (64 * QSTR * 2)        // 9216 bytes per 64x64 tile
#define AKV_B   (4 * ATILE_B)          // kh,kl,vh,vl = 36864 per stage
#define ASMEM (2 * ATILE_B + 2 * AKV_B) // qh,ql + 2 stages = 92160

__global__ __launch_bounds__(128, 2)
void attn_mma(const __nv_bfloat16* __restrict__ Qh, const __nv_bfloat16* __restrict__ Ql,
              const __nv_bfloat16* __restrict__ Kh, const __nv_bfloat16* __restrict__ Kl,
              const __nv_bfloat16* __restrict__ Vh, const __nv_bfloat16* __restrict__ Vl,
              float* __restrict__ Out)
{
    extern __shared__ char sm[];
    const uint32_t sb = smem_u32(sm);
    const int bh  = blockIdx.y;
    const int qt  = blockIdx.x;
    const int q0  = qt * 64;
    const int tid = threadIdx.x;
    const int lane = tid & 31;
    const int wid  = tid >> 5;

    const uint32_t oQ  = 0;                    // qh at 0, ql at ATILE_B
    const uint32_t oKV = 2 * ATILE_B;          // stages

    // ---- issue Q loads (group 0) ----
    {
        const __nv_bfloat16* qsrc[2] = { Qh + ((size_t)bh * Ll + q0) * 64,
                                         Ql + ((size_t)bh * Ll + q0) * 64 };
#pragma unroll
        for (int i = 0; i < 8; i++) {
            int idx = i * 128 + tid;           // 0..1023
            int t = idx >> 9, r = (idx >> 3) & 63, cc = idx & 7;
            cpa16(sb + oQ + t * ATILE_B + (uint32_t)(r * QSTR + cc * 8) * 2,
                  qsrc[t] + (size_t)r * 64 + cc * 8);
        }
        asm volatile("cp.async.commit_group;");
    }

    const int jstart = (qt < 24) ? qt : 24;
    const int nj = 32 - jstart;

    const __nv_bfloat16* kvsrc[4] = {
        Kh + (size_t)bh * Ll * 64, Kl + (size_t)bh * Ll * 64,
        Vh + (size_t)bh * Ll * 64, Vl + (size_t)bh * Ll * 64 };

    // ---- issue KV stage 0 (group 1) ----
    {
        const int kt = jstart * 64;
#pragma unroll
        for (int i = 0; i < 16; i++) {
            int idx = i * 128 + tid;           // 0..2047
            int t = idx >> 9, r = (idx >> 3) & 63, cc = idx & 7;
            cpa16(sb + oKV + t * ATILE_B + (uint32_t)(r * QSTR + cc * 8) * 2,
                  kvsrc[t] + (size_t)(kt + r) * 64 + cc * 8);
        }
        asm volatile("cp.async.commit_group;");
    }

    // ---- wait Q, build Q fragments ----
    asm volatile("cp.async.wait_group 1;");
    __syncthreads();

    uint32_t fqh[4][4], fql[4][4];
    {
        const uint32_t qaddr = sb + oQ +
            (uint32_t)((wid * 16 + (lane & 15)) * QSTR + (lane >> 4) * 8) * 2;
#pragma unroll
        for (int c = 0; c < 4; c++) {
            ldsm_x4(fqh[c], qaddr + c * 32);
            ldsm_x4(fql[c], qaddr + ATILE_B + c * 32);
        }
    }

    // per-thread softmax state (rows r1 = q0+wid*16+lane/4, r2 = r1+8)
    float m1 = -5e29f, m2 = -5e29f, l1 = 0.f, l2 = 0.f;
    float acc[8][4];
#pragma unroll
    for (int j = 0; j < 8; j++)
#pragma unroll
        for (int d = 0; d < 4; d++) acc[j][d] = 0.f;

    const int r1 = q0 + wid * 16 + (lane >> 2);

    // ldmatrix address components
    const uint32_t kaddr0 = (uint32_t)((((lane >> 4) << 3) + (lane & 7)) * QSTR
                                        + ((lane >> 3) & 1) * 8) * 2;
    const uint32_t vaddr0 = (uint32_t)((lane & 15) * QSTR + (lane >> 4) * 8) * 2;

    for (int tix = 0; tix < nj; tix++) {
        const int j = jstart + tix;
        const int kt = j * 64;
        const int st = tix & 1;

        if (tix + 1 < nj) {
            const int ktn = kt + 64;
            const uint32_t soff = oKV + (st ^ 1) * AKV_B;
#pragma unroll
            for (int i = 0; i < 16; i++) {
                int idx = i * 128 + tid;
                int t = idx >> 9, r = (idx >> 3) & 63, cc = idx & 7;
                cpa16(sb + soff + t * ATILE_B + (uint32_t)(r * QSTR + cc * 8) * 2,
                      kvsrc[t] + (size_t)(ktn + r) * 64 + cc * 8);
            }
            asm volatile("cp.async.commit_group;");
            asm volatile("cp.async.wait_group 1;");
        } else {
            asm volatile("cp.async.wait_group 0;");
        }
        __syncthreads();

        const uint32_t sKh = sb + oKV + st * AKV_B;
        const uint32_t sKl = sKh + ATILE_B;
        const uint32_t sVh = sKh + 2 * ATILE_B;
        const uint32_t sVl = sKh + 3 * ATILE_B;

        // ---- S = Q K^T (3-pass split) ----
        float s[8][4];
#pragma unroll
        for (int jb = 0; jb < 8; jb++)
#pragma unroll
            for (int d = 0; d < 4; d++) s[jb][d] = 0.f;

#pragma unroll
        for (int c = 0; c < 4; c++) {
            const uint32_t kb = c * 32;        // 16 cols * 2B
#pragma unroll
            for (int nt = 0; nt < 4; nt++) {
                uint32_t khf[4], klf[4];
                const uint32_t noff = (uint32_t)(nt * 16 * QSTR * 2) + kb;
                ldsm_x4(khf, sKh + kaddr0 + noff);
                ldsm_x4(klf, sKl + kaddr0 + noff);
                mma16816(s[nt * 2 + 0], fqh[c], &khf[0]);
                mma16816(s[nt * 2 + 1], fqh[c], &khf[2]);
                mma16816(s[nt * 2 + 0], fqh[c], &klf[0]);
                mma16816(s[nt * 2 + 1], fqh[c], &klf[2]);
                mma16816(s[nt * 2 + 0], fql[c], &khf[0]);
                mma16816(s[nt * 2 + 1], fql[c], &khf[2]);
            }
        }

        // ---- mask (diagonal tile only: kg > qi required) ----
        if (kt == q0 && kt < PAD) {
            const int cbase = kt + 2 * (lane & 3);
#pragma unroll
            for (int jb = 0; jb < 8; jb++) {
                const int c0 = cbase + jb * 8;
                s[jb][0] = (c0     > r1) ? s[jb][0] : -1e30f;
                s[jb][1] = (c0 + 1 > r1) ? s[jb][1] : -1e30f;
                s[jb][2] = (c0     > r1 + 8) ? s[jb][2] : -1e30f;
                s[jb][3] = (c0 + 1 > r1 + 8) ? s[jb][3] : -1e30f;
            }
        }

        // ---- online softmax ----
        float t1 = -1e30f, t2 = -1e30f;
#pragma unroll
        for (int jb = 0; jb < 8; jb++) {
            t1 = fmaxf(t1, fmaxf(s[jb][0], s[jb][1]));
            t2 = fmaxf(t2, fmaxf(s[jb][2], s[jb][3]));
        }
        t1 = fmaxf(t1, __shfl_xor_sync(0xffffffffu, t1, 1));
        t1 = fmaxf(t1, __shfl_xor_sync(0xffffffffu, t1, 2));
        t2 = fmaxf(t2, __shfl_xor_sync(0xffffffffu, t2, 1));
        t2 = fmaxf(t2, __shfl_xor_sync(0xffffffffu, t2, 2));

        const float mn1 = fmaxf(m1, t1);
        const float mn2 = fmaxf(m2, t2);
        const float a1 = __expf(m1 - mn1);
        const float a2 = __expf(m2 - mn2);
        m1 = mn1; m2 = mn2;

        float sum1 = 0.f, sum2 = 0.f;
#pragma unroll
        for (int jb = 0; jb < 8; jb++) {
            s[jb][0] = __expf(s[jb][0] - mn1);
            s[jb][1] = __expf(s[jb][1] - mn1);
            s[jb][2] = __expf(s[jb][2] - mn2);
            s[jb][3] = __expf(s[jb][3] - mn2);
            sum1 += s[jb][0] + s[jb][1];
            sum2 += s[jb][2] + s[jb][3];
        }
        sum1 += __shfl_xor_sync(0xffffffffu, sum1, 1);
        sum1 += __shfl_xor_sync(0xffffffffu, sum1, 2);
        sum2 += __shfl_xor_sync(0xffffffffu, sum2, 1);
        sum2 += __shfl_xor_sync(0xffffffffu, sum2, 2);
        l1 = l1 * a1 + sum1;
        l2 = l2 * a2 + sum2;

#pragma unroll
        for (int jb = 0; jb < 8; jb++) {
            acc[jb][0] *= a1; acc[jb][1] *= a1;
            acc[jb][2] *= a2; acc[jb][3] *= a2;
        }

        // ---- P fragments (hi/lo split from S registers) ----
        uint32_t fph[4][4], fpl[4][4];
#pragma unroll
        for (int c = 0; c < 4; c++) {
            const float* p0 = s[2 * c];
            const float* p1 = s[2 * c + 1];
            fph[c][0] = packbf(p0[0], p0[1]);
            fph[c][1] = packbf(p0[2], p0[3]);
            fph[c][2] = packbf(p1[0], p1[1]);
            fph[c][3] = packbf(p1[2], p1[3]);
#pragma unroll
            for (int r = 0; r < 4; r++) {
                __nv_bfloat162 hb = *(__nv_bfloat162*)&fph[c][r];
                const float* src = (r < 2) ? p0 : p1;
                const int o = (r & 1) * 2;
                fpl[c][r] = packbf(src[o] - __bfloat162float(hb.x),
                                   src[o + 1] - __bfloat162float(hb.y));
            }
        }

        // ---- O += P V (3-pass split), V via ldmatrix.trans ----
#pragma unroll
        for (int c = 0; c < 4; c++) {
            const uint32_t roff = (uint32_t)(c * 16 * QSTR * 2);
#pragma unroll
            for (int ng = 0; ng < 4; ng++) {
                uint32_t vhf[4], vlf[4];
                const uint32_t aoff = roff + vaddr0 + (uint32_t)(ng * 16 * 2);
                ldsm_x4_t(vhf, sVh + aoff);
                ldsm_x4_t(vlf, sVl + aoff);
                mma16816(acc[ng * 2 + 0], fph[c], &vhf[0]);
                mma16816(acc[ng * 2 + 1], fph[c], &vhf[2]);
                mma16816(acc[ng * 2 + 0], fph[c], &vlf[0]);
                mma16816(acc[ng * 2 + 1], fph[c], &vlf[2]);
                mma16816(acc[ng * 2 + 0], fpl[c], &vhf[0]);
                mma16816(acc[ng * 2 + 1], fpl[c], &vhf[2]);
            }
        }
        __syncthreads();
    }

    // ---- epilogue: Out[B,L,H*Dh] fp32 ----
    const int b = bh >> 4;
    const int h = bh & 15;
    const float inv1 = 1.f / l1;
    const float inv2 = 1.f / l2;
    const size_t row1 = (size_t)(b * Ll) + r1;   // within batch b: row index q
    float* o1 = Out + row1 * Dm + h * 64 + 2 * (lane & 3);
    float* o2 = o1 + 8 * (size_t)Dm;
#pragma unroll
    for (int jb = 0; jb < 8; jb++) {
        float2 w1, w2;
        w1.x = acc[jb][0] * inv1; w1.y = acc[jb][1] * inv1;
        w2.x = acc[jb][2] * inv2; w2.y = acc[jb][3] * inv2;
        *(float2*)(o1 + jb * 8) = w1;
        *(float2*)(o2 + jb * 8) = w2;
    }
}

// ---------------------------------------------------------------------------
// Launch
// Inputs (metadata order): x, pad_mask, Wqkv, bqkv, Wout, bout
// ---------------------------------------------------------------------------
extern "C" void kernel_launch(void* const* d_in, const int* in_sizes, int n_in,
                              void* d_out, int out_size)
{
    const float* x    = (const float*)d_in[0];
    const float* Wqkv = (const float*)d_in[2];
    const float* bqkv = (const float*)d_in[3];
    const float* Wout = (const float*)d_in[4];
    const float* bout = (const float*)d_in[5];
    float* out = (float*)d_out;

    float *qkv, *attn;
    __nv_bfloat16 *ah, *al, *bhp, *blp, *qh, *ql, *kh, *kl, *vh, *vl;
    cudaGetSymbolAddress((void**)&qkv,  g_qkv);
    cudaGetSymbolAddress((void**)&attn, g_attn);
    cudaGetSymbolAddress((void**)&ah,   g_ah);
    cudaGetSymbolAddress((void**)&al,   g_al);
    cudaGetSymbolAddress((void**)&bhp,  g_bh);
    cudaGetSymbolAddress((void**)&blp,  g_bl);
    cudaGetSymbolAddress((void**)&qh,   g_qh);
    cudaGetSymbolAddress((void**)&ql,   g_ql);
    cudaGetSymbolAddress((void**)&kh,   g_kh);
    cudaGetSymbolAddress((void**)&kl,   g_kl);
    cudaGetSymbolAddress((void**)&vh,   g_vh);
    cudaGetSymbolAddress((void**)&vl,   g_vl);

    cudaFuncSetAttribute(gemm_mma_split, cudaFuncAttributeMaxDynamicSharedMemorySize, GSMEM);
    cudaFuncSetAttribute(attn_mma, cudaFuncAttributeMaxDynamicSharedMemorySize, ASMEM);

    // 1) split x and Wqkv into bf16 hi/lo
    {
        int n2 = (Mrows * Dm) / 2;
        split_bf16<<<(n2 + 255) / 256, 256>>>(x, ah, al, n2);
        n2 = (QKVN * Dm) / 2;
        split_bf16<<<(n2 + 255) / 256, 256>>>(Wqkv, bhp, blp, n2);
    }
    // 2) QKV projection + bias
    {
        dim3 grid(QKVN / 128, Mrows / 128);
        gemm_mma_split<<<grid, 256, GSMEM>>>(ah, al, bhp, blp, bqkv, qkv, Mrows, QKVN, Dm);
    }
    // 3) RoPE + split + scatter
    {
        int total = Bb * Ll * Hh * (DhD / 2);
        rope_scatter<<<(total + 255) / 256, 256>>>(qkv, qh, ql, kh, kl, vh, vl);
    }
    // 4) attention (tensor cores)
    {
        dim3 grid(Ll / 64, Bb * Hh);
        attn_mma<<<grid, 128, ASMEM>>>(qh, ql, kh, kl, vh, vl, attn);
    }
    // 5) split attn output and Wout
    {
        int n2 = (Mrows * Dm) / 2;
        split_bf16<<<(n2 + 255) / 256, 256>>>(attn, ah, al, n2);
        n2 = (Dm * Dm) / 2;
        split_bf16<<<(n2 + 255) / 256, 256>>>(Wout, bhp, blp, n2);
    }
    // 6) output projection + bias
    {
        dim3 grid(Dm / 128, Mrows / 128);
        gemm_mma_split<<<grid, 256, GSMEM>>>(ah, al, bhp, blp, bout, out, Mrows, Dm, Dm);
    }
}

// round 9
// speedup vs baseline: 3.5403x; 1.0115x over previous
#include <cuda_runtime.h>
#include <cuda_bf16.h>
#include <cstdint>
#include <math.h>

// Problem constants (fixed by the dataset)
#define Bb   2
#define Ll   2048
#define Dm   1024
#define Hh   16
#define DhD  64
#define PAD  1536
#define Mrows (Bb * Ll)          // 4096
#define QKVN  (3 * Dm)           // 3072

// ---------------------------------------------------------------------------
// Scratch (device globals; no runtime allocation allowed)
// ---------------------------------------------------------------------------
// bf16 split buffers for GEMMs (A: x, then attn-out written by attention;
// B: Wqkv then Wout)
__device__ __nv_bfloat16 g_ah[(size_t)Mrows * Dm];
__device__ __nv_bfloat16 g_al[(size_t)Mrows * Dm];
__device__ __nv_bfloat16 g_bh[(size_t)QKVN * Dm];
__device__ __nv_bfloat16 g_bl[(size_t)QKVN * Dm];
// bf16 hi/lo q/k/v in [B*H][L][64] layout (q pre-scaled by 1/8)
#define QKVSZ ((size_t)Bb * Hh * Ll * DhD)
__device__ __nv_bfloat16 g_qh[QKVSZ], g_ql[QKVSZ];
__device__ __nv_bfloat16 g_kh[QKVSZ], g_kl[QKVSZ];
__device__ __nv_bfloat16 g_vh[QKVSZ], g_vl[QKVSZ];
// RoPE cos/sin table: [L][32] -> float2(cos, sin)
__device__ float2 g_rope[Ll * 32];

// ---------------------------------------------------------------------------
// mma.sync helpers (baseline PTX features, compile for compute_103)
// ---------------------------------------------------------------------------
__device__ __forceinline__ uint32_t smem_u32(const void* p) {
    uint32_t a;
    asm("{ .reg .u64 t; cvta.to.shared.u64 t, %1; cvt.u32.u64 %0, t; }" : "=r"(a) : "l"(p));
    return a;
}
__device__ __forceinline__ void ldsm_x4(uint32_t r[4], uint32_t addr) {
    asm volatile("ldmatrix.sync.aligned.m8n8.x4.shared.b16 {%0,%1,%2,%3}, [%4];"
                 : "=r"(r[0]), "=r"(r[1]), "=r"(r[2]), "=r"(r[3]) : "r"(addr));
}
__device__ __forceinline__ void ldsm_x4_t(uint32_t r[4], uint32_t addr) {
    asm volatile("ldmatrix.sync.aligned.m8n8.x4.trans.shared.b16 {%0,%1,%2,%3}, [%4];"
                 : "=r"(r[0]), "=r"(r[1]), "=r"(r[2]), "=r"(r[3]) : "r"(addr));
}
__device__ __forceinline__ void mma16816(float c[4], const uint32_t a[4], const uint32_t b[2]) {
    asm("mma.sync.aligned.m16n8k16.row.col.f32.bf16.bf16.f32 "
        "{%0,%1,%2,%3}, {%4,%5,%6,%7}, {%8,%9}, {%0,%1,%2,%3};"
        : "+f"(c[0]), "+f"(c[1]), "+f"(c[2]), "+f"(c[3])
        : "r"(a[0]), "r"(a[1]), "r"(a[2]), "r"(a[3]), "r"(b[0]), "r"(b[1]));
}
__device__ __forceinline__ void cpa16(uint32_t dst, const void* src) {
    asm volatile("cp.async.cg.shared.global [%0], [%1], 16;" :: "r"(dst), "l"(src));
}
__device__ __forceinline__ uint32_t packbf(float lo, float hi) {
    uint32_t r;
    asm("cvt.rn.bf16x2.f32 %0, %1, %2;" : "=r"(r) : "f"(hi), "f"(lo));
    return r;
}
__device__ __forceinline__ void split2(float2 v, __nv_bfloat162& h, __nv_bfloat162& l) {
    h.x = __float2bfloat16(v.x); h.y = __float2bfloat16(v.y);
    l.x = __float2bfloat16(v.x - __bfloat162float(h.x));
    l.y = __float2bfloat16(v.y - __bfloat162float(h.y));
}

// ---------------------------------------------------------------------------
// Kernel: fp32 -> (bf16 hi, bf16 lo) split, 2 elements/thread
// ---------------------------------------------------------------------------
__global__ __launch_bounds__(256)
void split_bf16(const float* __restrict__ X, __nv_bfloat16* __restrict__ H,
                __nv_bfloat16* __restrict__ Lo, int n2)
{
    int i = blockIdx.x * blockDim.x + threadIdx.x;
    if (i >= n2) return;
    float2 x = ((const float2*)X)[i];
    __nv_bfloat162 hv, lv;
    split2(x, hv, lv);
    ((__nv_bfloat162*)H)[i]  = hv;
    ((__nv_bfloat162*)Lo)[i] = lv;
}

// ---------------------------------------------------------------------------
// Kernel: RoPE cos/sin table
// ---------------------------------------------------------------------------
__global__ __launch_bounds__(256)
void rope_table(float2* __restrict__ T)
{
    int idx = blockIdx.x * blockDim.x + threadIdx.x;
    if (idx >= Ll * 32) return;
    const int l = idx >> 5, j = idx & 31;
    const float inv_freq = __expf(-(float)j * (9.210340371976184f / 32.0f));
    float s, c;
    sincosf((float)l * inv_freq, &s, &c);
    T[idx] = make_float2(c, s);
}

// ---------------------------------------------------------------------------
// mma.sync bf16-split GEMM: C = (Ah+Al)(Bh+Bl)^T + bias, 3-term split.
// EPI=0: plain fp32 C+bias store.
// EPI=1: fused bias + RoPE + bf16 hi/lo split scatter to q/k/v buffers.
// ---------------------------------------------------------------------------
#define PADW 40
#define KC   32
#define TILE_BYTES (128 * PADW * 2)
#define STAGE_BYTES (4 * TILE_BYTES)
#define GSMEM (2 * STAGE_BYTES)

template<int EPI>
__global__ __launch_bounds__(256, 2)
void gemm_mma_split(const __nv_bfloat16* __restrict__ Ah, const __nv_bfloat16* __restrict__ Al,
                    const __nv_bfloat16* __restrict__ Bh, const __nv_bfloat16* __restrict__ Bl,
                    const float* __restrict__ bias, float* __restrict__ C,
                    __nv_bfloat16* __restrict__ Qh, __nv_bfloat16* __restrict__ Ql,
                    __nv_bfloat16* __restrict__ Kh, __nv_bfloat16* __restrict__ Kl,
                    __nv_bfloat16* __restrict__ Vh, __nv_bfloat16* __restrict__ Vl,
                    const float2* __restrict__ Rt,
                    int M, int N, int K)
{
    extern __shared__ char dsm[];
    const uint32_t sbase = smem_u32(dsm);

    const int tid  = threadIdx.x;
    const int lane = tid & 31;
    const int wid  = tid >> 5;
    const int wm   = wid & 3;
    const int wn   = wid >> 2;
    const int m0   = blockIdx.y * 128;
    const int n0   = blockIdx.x * 128;

    float c[2][8][4];
#pragma unroll
    for (int i = 0; i < 2; i++)
#pragma unroll
        for (int j = 0; j < 8; j++)
#pragma unroll
            for (int q = 0; q < 4; q++) c[i][j][q] = 0.f;

    const int lr  = tid >> 2;
    const int lcc = (tid & 3) * 8;
    const __nv_bfloat16* srcs[4] = {
        Ah + (size_t)(m0 + lr) * K + lcc,  Al + (size_t)(m0 + lr) * K + lcc,
        Bh + (size_t)(n0 + lr) * K + lcc,  Bl + (size_t)(n0 + lr) * K + lcc };
    const size_t rowskip = (size_t)64 * K;
    const uint32_t dst0 = sbase + (uint32_t)(lr * PADW + lcc) * 2;
    const uint32_t dst1 = dst0 + (uint32_t)(64 * PADW) * 2;

    const int arow = wm * 32 + (lane & 15);
    const int acol = (lane >> 4) * 8;
    const int brow = wn * 64 + ((lane >> 4) << 3) + (lane & 7);
    const int bcol = ((lane >> 3) & 1) * 8;
    const uint32_t aAh = sbase + 0 * TILE_BYTES + (uint32_t)(arow * PADW + acol) * 2;
    const uint32_t aAl = sbase + 1 * TILE_BYTES + (uint32_t)(arow * PADW + acol) * 2;
    const uint32_t aBh = sbase + 2 * TILE_BYTES + (uint32_t)(brow * PADW + bcol) * 2;
    const uint32_t aBl = sbase + 3 * TILE_BYTES + (uint32_t)(brow * PADW + bcol) * 2;

    const int nch = K / KC;

#pragma unroll
    for (int t = 0; t < 4; t++) {
        const uint32_t toff = t * TILE_BYTES;
        cpa16(dst0 + toff, srcs[t]);
        cpa16(dst1 + toff, srcs[t] + rowskip);
    }
    asm volatile("cp.async.commit_group;");

    for (int s = 0; s < nch; s++) {
        if (s + 1 < nch) {
            const uint32_t stoff = ((s + 1) & 1) * (uint32_t)STAGE_BYTES;
            const int koff = (s + 1) * KC;
#pragma unroll
            for (int t = 0; t < 4; t++) {
                const uint32_t toff = stoff + t * TILE_BYTES;
                cpa16(dst0 + toff, srcs[t] + koff);
                cpa16(dst1 + toff, srcs[t] + koff + rowskip);
            }
            asm volatile("cp.async.commit_group;");
            asm volatile("cp.async.wait_group 1;");
        } else {
            asm volatile("cp.async.wait_group 0;");
        }
        __syncthreads();

        const uint32_t stoff = (s & 1) * (uint32_t)STAGE_BYTES;
#pragma unroll
        for (int ks = 0; ks < 2; ks++) {
            const uint32_t kb = (uint32_t)(ks * 16 * 2);
            uint32_t ahf[2][4], alf[2][4];
#pragma unroll
            for (int mt = 0; mt < 2; mt++) {
                const uint32_t moff = stoff + (uint32_t)(mt * 16 * PADW * 2) + kb;
                ldsm_x4(ahf[mt], aAh + moff);
                ldsm_x4(alf[mt], aAl + moff);
            }
#pragma unroll
            for (int nt = 0; nt < 4; nt++) {
                uint32_t bhf[4], blf[4];
                const uint32_t noff = stoff + (uint32_t)(nt * 16 * PADW * 2) + kb;
                ldsm_x4(bhf, aBh + noff);
                ldsm_x4(blf, aBl + noff);
                mma16816(c[0][nt * 2 + 0], ahf[0], &bhf[0]);
                mma16816(c[0][nt * 2 + 1], ahf[0], &bhf[2]);
                mma16816(c[1][nt * 2 + 0], ahf[1], &bhf[0]);
                mma16816(c[1][nt * 2 + 1], ahf[1], &bhf[2]);
                mma16816(c[0][nt * 2 + 0], ahf[0], &blf[0]);
                mma16816(c[0][nt * 2 + 1], ahf[0], &blf[2]);
                mma16816(c[1][nt * 2 + 0], ahf[1], &blf[0]);
                mma16816(c[1][nt * 2 + 1], ahf[1], &blf[2]);
                mma16816(c[0][nt * 2 + 0], alf[0], &bhf[0]);
                mma16816(c[0][nt * 2 + 1], alf[0], &bhf[2]);
                mma16816(c[1][nt * 2 + 0], alf[1], &bhf[0]);
                mma16816(c[1][nt * 2 + 1], alf[1], &bhf[2]);
            }
        }
        __syncthreads();
    }

#pragma unroll
    for (int mt = 0; mt < 2; mt++) {
        const int mrow = m0 + wm * 32 + mt * 16 + (lane >> 2);
#pragma unroll
        for (int n8 = 0; n8 < 8; n8++) {
            const int ncol = n0 + wn * 64 + n8 * 8 + 2 * (lane & 3);
            float2 bb = *(const float2*)(bias + ncol);
            if (EPI == 0) {
                float2 o0, o1;
                o0.x = c[mt][n8][0] + bb.x; o0.y = c[mt][n8][1] + bb.y;
                o1.x = c[mt][n8][2] + bb.x; o1.y = c[mt][n8][3] + bb.y;
                *(float2*)&C[(size_t)mrow * N + ncol]       = o0;
                *(float2*)&C[(size_t)(mrow + 8) * N + ncol] = o1;
            } else {
                const int sec  = ncol >> 10;        // 0=q, 1=k, 2=v
                const int hcol = ncol & 1023;
                const int hh   = hcol >> 6;
                const int j    = (hcol & 63) >> 1;  // rope pair index
                __nv_bfloat16* Hd = (sec == 0) ? Qh : (sec == 1) ? Kh : Vh;
                __nv_bfloat16* Ld = (sec == 0) ? Ql : (sec == 1) ? Kl : Vl;
#pragma unroll
                for (int r = 0; r < 2; r++) {
                    const int mr = mrow + r * 8;
                    const int l  = mr & (Ll - 1);
                    const int b  = mr >> 11;
                    float2 v;
                    v.x = c[mt][n8][2 * r]     + bb.x;
                    v.y = c[mt][n8][2 * r + 1] + bb.y;
                    if (sec < 2) {
                        const float2 cs = Rt[l * 32 + j];
                        float nx = v.x * cs.x - v.y * cs.y;
                        float ny = v.x * cs.y + v.y * cs.x;
                        if (sec == 0) { nx *= 0.125f; ny *= 0.125f; }
                        v.x = nx; v.y = ny;
                    }
                    __nv_bfloat162 hv, lv;
                    split2(v, hv, lv);
                    const size_t base = ((size_t)(b * Hh + hh) * Ll + l) * 32 + j;
                    ((__nv_bfloat162*)Hd)[base] = hv;
                    ((__nv_bfloat162*)Ld)[base] = lv;
                }
            }
        }
    }
}

// ---------------------------------------------------------------------------
// Flash attention with mma.sync bf16-split (inverted mask).
// Epilogue writes bf16 hi/lo directly into the out-proj A buffers.
// ---------------------------------------------------------------------------
#define QSTR 72
#define ATILE_B (64 * QSTR * 2)
#define AKV_B   (4 * ATILE_B)
#define ASMEM (2 * ATILE_B + 2 * AKV_B)

__global__ __launch_bounds__(128, 2)
void attn_mma(const __nv_bfloat16* __restrict__ Qh, const __nv_bfloat16* __restrict__ Ql,
              const __nv_bfloat16* __restrict__ Kh, const __nv_bfloat16* __restrict__ Kl,
              const __nv_bfloat16* __restrict__ Vh, const __nv_bfloat16* __restrict__ Vl,
              __nv_bfloat16* __restrict__ OAh, __nv_bfloat16* __restrict__ OAl)
{
    extern __shared__ char sm[];
    const uint32_t sb = smem_u32(sm);
    const int bh  = blockIdx.y;
    const int qt  = blockIdx.x;
    const int q0  = qt * 64;
    const int tid = threadIdx.x;
    const int lane = tid & 31;
    const int wid  = tid >> 5;

    const uint32_t oQ  = 0;
    const uint32_t oKV = 2 * ATILE_B;

    {
        const __nv_bfloat16* qsrc[2] = { Qh + ((size_t)bh * Ll + q0) * 64,
                                         Ql + ((size_t)bh * Ll + q0) * 64 };
#pragma unroll
        for (int i = 0; i < 8; i++) {
            int idx = i * 128 + tid;
            int t = idx >> 9, r = (idx >> 3) & 63, cc = idx & 7;
            cpa16(sb + oQ + t * ATILE_B + (uint32_t)(r * QSTR + cc * 8) * 2,
                  qsrc[t] + (size_t)r * 64 + cc * 8);
        }
        asm volatile("cp.async.commit_group;");
    }

    const int jstart = (qt < 24) ? qt : 24;
    const int nj = 32 - jstart;

    const __nv_bfloat16* kvsrc[4] = {
        Kh + (size_t)bh * Ll * 64, Kl + (size_t)bh * Ll * 64,
        Vh + (size_t)bh * Ll * 64, Vl + (size_t)bh * Ll * 64 };

    {
        const int kt = jstart * 64;
#pragma unroll
        for (int i = 0; i < 16; i++) {
            int idx = i * 128 + tid;
            int t = idx >> 9, r = (idx >> 3) & 63, cc = idx & 7;
            cpa16(sb + oKV + t * ATILE_B + (uint32_t)(r * QSTR + cc * 8) * 2,
                  kvsrc[t] + (size_t)(kt + r) * 64 + cc * 8);
        }
        asm volatile("cp.async.commit_group;");
    }

    asm volatile("cp.async.wait_group 1;");
    __syncthreads();

    uint32_t fqh[4][4], fql[4][4];
    {
        const uint32_t qaddr = sb + oQ +
            (uint32_t)((wid * 16 + (lane & 15)) * QSTR + (lane >> 4) * 8) * 2;
#pragma unroll
        for (int c = 0; c < 4; c++) {
            ldsm_x4(fqh[c], qaddr + c * 32);
            ldsm_x4(fql[c], qaddr + ATILE_B + c * 32);
        }
    }

    float m1 = -5e29f, m2 = -5e29f, l1 = 0.f, l2 = 0.f;
    float acc[8][4];
#pragma unroll
    for (int j = 0; j < 8; j++)
#pragma unroll
        for (int d = 0; d < 4; d++) acc[j][d] = 0.f;

    const int r1 = q0 + wid * 16 + (lane >> 2);

    const uint32_t kaddr0 = (uint32_t)((((lane >> 4) << 3) + (lane & 7)) * QSTR
                                        + ((lane >> 3) & 1) * 8) * 2;
    const uint32_t vaddr0 = (uint32_t)((lane & 15) * QSTR + (lane >> 4) * 8) * 2;

    for (int tix = 0; tix < nj; tix++) {
        const int j = jstart + tix;
        const int kt = j * 64;
        const int st = tix & 1;

        if (tix + 1 < nj) {
            const int ktn = kt + 64;
            const uint32_t soff = oKV + (st ^ 1) * AKV_B;
#pragma unroll
            for (int i = 0; i < 16; i++) {
                int idx = i * 128 + tid;
                int t = idx >> 9, r = (idx >> 3) & 63, cc = idx & 7;
                cpa16(sb + soff + t * ATILE_B + (uint32_t)(r * QSTR + cc * 8) * 2,
                      kvsrc[t] + (size_t)(ktn + r) * 64 + cc * 8);
            }
            asm volatile("cp.async.commit_group;");
            asm volatile("cp.async.wait_group 1;");
        } else {
            asm volatile("cp.async.wait_group 0;");
        }
        __syncthreads();

        const uint32_t sKh = sb + oKV + st * AKV_B;
        const uint32_t sKl = sKh + ATILE_B;
        const uint32_t sVh = sKh + 2 * ATILE_B;
        const uint32_t sVl = sKh + 3 * ATILE_B;

        float s[8][4];
#pragma unroll
        for (int jb = 0; jb < 8; jb++)
#pragma unroll
            for (int d = 0; d < 4; d++) s[jb][d] = 0.f;

#pragma unroll
        for (int c = 0; c < 4; c++) {
            const uint32_t kb = c * 32;
#pragma unroll
            for (int nt = 0; nt < 4; nt++) {
                uint32_t khf[4], klf[4];
                const uint32_t noff = (uint32_t)(nt * 16 * QSTR * 2) + kb;
                ldsm_x4(khf, sKh + kaddr0 + noff);
                ldsm_x4(klf, sKl + kaddr0 + noff);
                mma16816(s[nt * 2 + 0], fqh[c], &khf[0]);
                mma16816(s[nt * 2 + 1], fqh[c], &khf[2]);
                mma16816(s[nt * 2 + 0], fqh[c], &klf[0]);
                mma16816(s[nt * 2 + 1], fqh[c], &klf[2]);
                mma16816(s[nt * 2 + 0], fql[c], &khf[0]);
                mma16816(s[nt * 2 + 1], fql[c], &khf[2]);
            }
        }

        if (kt == q0 && kt < PAD) {
            const int cbase = kt + 2 * (lane & 3);
#pragma unroll
            for (int jb = 0; jb < 8; jb++) {
                const int c0 = cbase + jb * 8;
                s[jb][0] = (c0     > r1) ? s[jb][0] : -1e30f;
                s[jb][1] = (c0 + 1 > r1) ? s[jb][1] : -1e30f;
                s[jb][2] = (c0     > r1 + 8) ? s[jb][2] : -1e30f;
                s[jb][3] = (c0 + 1 > r1 + 8) ? s[jb][3] : -1e30f;
            }
        }

        float t1 = -1e30f, t2 = -1e30f;
#pragma unroll
        for (int jb = 0; jb < 8; jb++) {
            t1 = fmaxf(t1, fmaxf(s[jb][0], s[jb][1]));
            t2 = fmaxf(t2, fmaxf(s[jb][2], s[jb][3]));
        }
        t1 = fmaxf(t1, __shfl_xor_sync(0xffffffffu, t1, 1));
        t1 = fmaxf(t1, __shfl_xor_sync(0xffffffffu, t1, 2));
        t2 = fmaxf(t2, __shfl_xor_sync(0xffffffffu, t2, 1));
        t2 = fmaxf(t2, __shfl_xor_sync(0xffffffffu, t2, 2));

        const float mn1 = fmaxf(m1, t1);
        const float mn2 = fmaxf(m2, t2);
        const float a1 = __expf(m1 - mn1);
        const float a2 = __expf(m2 - mn2);
        m1 = mn1; m2 = mn2;

        float sum1 = 0.f, sum2 = 0.f;
#pragma unroll
        for (int jb = 0; jb < 8; jb++) {
            s[jb][0] = __expf(s[jb][0] - mn1);
            s[jb][1] = __expf(s[jb][1] - mn1);
            s[jb][2] = __expf(s[jb][2] - mn2);
            s[jb][3] = __expf(s[jb][3] - mn2);
            sum1 += s[jb][0] + s[jb][1];
            sum2 += s[jb][2] + s[jb][3];
        }
        sum1 += __shfl_xor_sync(0xffffffffu, sum1, 1);
        sum1 += __shfl_xor_sync(0xffffffffu, sum1, 2);
        sum2 += __shfl_xor_sync(0xffffffffu, sum2, 1);
        sum2 += __shfl_xor_sync(0xffffffffu, sum2, 2);
        l1 = l1 * a1 + sum1;
        l2 = l2 * a2 + sum2;

#pragma unroll
        for (int jb = 0; jb < 8; jb++) {
            acc[jb][0] *= a1; acc[jb][1] *= a1;
            acc[jb][2] *= a2; acc[jb][3] *= a2;
        }

        uint32_t fph[4][4], fpl[4][4];
#pragma unroll
        for (int c = 0; c < 4; c++) {
            const float* p0 = s[2 * c];
            const float* p1 = s[2 * c + 1];
            fph[c][0] = packbf(p0[0], p0[1]);
            fph[c][1] = packbf(p0[2], p0[3]);
            fph[c][2] = packbf(p1[0], p1[1]);
            fph[c][3] = packbf(p1[2], p1[3]);
#pragma unroll
            for (int r = 0; r < 4; r++) {
                __nv_bfloat162 hb = *(__nv_bfloat162*)&fph[c][r];
                const float* src = (r < 2) ? p0 : p1;
                const int o = (r & 1) * 2;
                fpl[c][r] = packbf(src[o] - __bfloat162float(hb.x),
                                   src[o + 1] - __bfloat162float(hb.y));
            }
        }

#pragma unroll
        for (int c = 0; c < 4; c++) {
            const uint32_t roff = (uint32_t)(c * 16 * QSTR * 2);
#pragma unroll
            for (int ng = 0; ng < 4; ng++) {
                uint32_t vhf[4], vlf[4];
                const uint32_t aoff = roff + vaddr0 + (uint32_t)(ng * 16 * 2);
                ldsm_x4_t(vhf, sVh + aoff);
                ldsm_x4_t(vlf, sVl + aoff);
                mma16816(acc[ng * 2 + 0], fph[c], &vhf[0]);
                mma16816(acc[ng * 2 + 1], fph[c], &vhf[2]);
                mma16816(acc[ng * 2 + 0], fph[c], &vlf[0]);
                mma16816(acc[ng * 2 + 1], fph[c], &vlf[2]);
                mma16816(acc[ng * 2 + 0], fpl[c], &vhf[0]);
                mma16816(acc[ng * 2 + 1], fpl[c], &vhf[2]);
            }
        }
        __syncthreads();
    }

    // ---- epilogue: split to bf16 hi/lo, write out-proj A buffers [M][1024] ----
    const int b = bh >> 4;
    const int hh = bh & 15;
    const float inv1 = 1.f / l1;
    const float inv2 = 1.f / l2;
    const size_t row1 = (size_t)(b * Ll) + r1;
    const int col0 = hh * 64 + 2 * (lane & 3);
    __nv_bfloat162* H1 = (__nv_bfloat162*)OAh + row1 * (Dm / 2) + (col0 >> 1);
    __nv_bfloat162* L1 = (__nv_bfloat162*)OAl + row1 * (Dm / 2) + (col0 >> 1);
    __nv_bfloat162* H2 = H1 + 8 * (Dm / 2);
    __nv_bfloat162* L2 = L1 + 8 * (Dm / 2);
#pragma unroll
    for (int jb = 0; jb < 8; jb++) {
        float2 w1, w2;
        w1.x = acc[jb][0] * inv1; w1.y = acc[jb][1] * inv1;
        w2.x = acc[jb][2] * inv2; w2.y = acc[jb][3] * inv2;
        __nv_bfloat162 hv, lv;
        split2(w1, hv, lv); H1[jb * 4] = hv; L1[jb * 4] = lv;
        split2(w2, hv, lv); H2[jb * 4] = hv; L2[jb * 4] = lv;
    }
}

// ---------------------------------------------------------------------------
// Launch
// Inputs (metadata order): x, pad_mask, Wqkv, bqkv, Wout, bout
// ---------------------------------------------------------------------------
extern "C" void kernel_launch(void* const* d_in, const int* in_sizes, int n_in,
                              void* d_out, int out_size)
{
    const float* x    = (const float*)d_in[0];
    const float* Wqkv = (const float*)d_in[2];
    const float* bqkv = (const float*)d_in[3];
    const float* Wout = (const float*)d_in[4];
    const float* bout = (const float*)d_in[5];
    float* out = (float*)d_out;

    __nv_bfloat16 *ah, *al, *bhp, *blp, *qh, *ql, *kh, *kl, *vh, *vl;
    float2* rt;
    cudaGetSymbolAddress((void**)&ah,   g_ah);
    cudaGetSymbolAddress((void**)&al,   g_al);
    cudaGetSymbolAddress((void**)&bhp,  g_bh);
    cudaGetSymbolAddress((void**)&blp,  g_bl);
    cudaGetSymbolAddress((void**)&qh,   g_qh);
    cudaGetSymbolAddress((void**)&ql,   g_ql);
    cudaGetSymbolAddress((void**)&kh,   g_kh);
    cudaGetSymbolAddress((void**)&kl,   g_kl);
    cudaGetSymbolAddress((void**)&vh,   g_vh);
    cudaGetSymbolAddress((void**)&vl,   g_vl);
    cudaGetSymbolAddress((void**)&rt,   g_rope);

    cudaFuncSetAttribute(gemm_mma_split<0>, cudaFuncAttributeMaxDynamicSharedMemorySize, GSMEM);
    cudaFuncSetAttribute(gemm_mma_split<1>, cudaFuncAttributeMaxDynamicSharedMemorySize, GSMEM);
    cudaFuncSetAttribute(attn_mma, cudaFuncAttributeMaxDynamicSharedMemorySize, ASMEM);

    // 1) rope table + split x and Wqkv into bf16 hi/lo
    {
        rope_table<<<(Ll * 32 + 255) / 256, 256>>>(rt);
        int n2 = (Mrows * Dm) / 2;
        split_bf16<<<(n2 + 255) / 256, 256>>>(x, ah, al, n2);
        n2 = (QKVN * Dm) / 2;
        split_bf16<<<(n2 + 255) / 256, 256>>>(Wqkv, bhp, blp, n2);
    }
    // 2) QKV projection + bias + RoPE + split scatter (fused epilogue)
    {
        dim3 grid(QKVN / 128, Mrows / 128);
        gemm_mma_split<1><<<grid, 256, GSMEM>>>(ah, al, bhp, blp, bqkv, nullptr,
                                                qh, ql, kh, kl, vh, vl, rt,
                                                Mrows, QKVN, Dm);
    }
    // 3) attention (tensor cores), writes bf16 hi/lo out-proj A directly
    {
        dim3 grid(Ll / 64, Bb * Hh);
        attn_mma<<<grid, 128, ASMEM>>>(qh, ql, kh, kl, vh, vl, ah, al);
    }
    // 4) split Wout
    {
        int n2 = (Dm * Dm) / 2;
        split_bf16<<<(n2 + 255) / 256, 256>>>(Wout, bhp, blp, n2);
    }
    // 5) output projection + bias
    {
        dim3 grid(Dm / 128, Mrows / 128);
        gemm_mma_split<0><<<grid, 256, GSMEM>>>(ah, al, bhp, blp, bout, out,
                                                nullptr, nullptr, nullptr, nullptr,
                                                nullptr, nullptr, nullptr,
                                                Mrows, Dm, Dm);
    }
}